// round 3
// baseline (speedup 1.0000x reference)
#include <cuda_runtime.h>
#include <math.h>

// ---------------------------------------------------------------------------
// ChamferLoss: bidirectional chamfer distance between pred (Np x 3) and gt
// (Ng x 3) f32 point sets.
//
// out = mean_i sqrt(min_j d2(x_i, y_j)) + mean_j sqrt(min_i d2(x_i, y_j))
//
//   - min over d2 (sqrt is monotone) -> sqrt only 2*16K values at the end.
//   - expansion form d2 = (|x|^2 + |y|^2) - 2 x.y (matches reference math).
//     Per-pair: xdot = fma(c0,xx, fma(c1,xy, fma(c2,xz, x2))) (3 FFMA).
//       col-min tracks xdot directly (w_k constant over the min-over-rows;
//       added once per (tile,k) after the reduction).
//       row-min tracks xdot + w_k (1 FADD per pair).
//   - d2 may be slightly negative (cancellation) -> clamp with fmaxf ONLY at
//     reduction boundaries (uint-bit atomicMin needs non-negative floats).
//   - One pass over all pairs yields BOTH directional mins:
//       * block owns BX=128 x rows; row mins combined in shared, then one
//         global atomicMin per row (GY writers per row).
//       * col mins: shfl-xor across the 16 threads sharing a y slot, then
//         one global atomicMin per (block, y slot).
//   - grid = (Np/BX, GY) = 256 CTAs so all 148 SMs stay busy.
// ---------------------------------------------------------------------------

#define BX   128     // x rows per block
#define TILE 128     // y points per shared tile
#define GY   2       // y-direction split
#define NTHREADS 256
#define INF_BITS 0x7f800000u
#define PAD_COORD 1.0e18f

__device__ unsigned g_rowmin[65536];
__device__ unsigned g_colmin[65536];

__global__ void chamfer_init(int np, int m) {
    int i = blockIdx.x * blockDim.x + threadIdx.x;
    if (i < np) g_rowmin[i] = INF_BITS;
    if (i < m)  g_colmin[i] = INF_BITS;
}

__global__ void __launch_bounds__(NTHREADS) chamfer_main(
    const float* __restrict__ X, const float* __restrict__ Y,
    int np, int m)
{
    __shared__ float sy[TILE * 4];      // -2yx, -2yy, -2yz, |y|^2
    __shared__ unsigned srow[BX];

    const int tid = threadIdx.x;
    const int tx = tid & 15;   // x group: rows tx*8 .. tx*8+7 of this block
    const int ty = tid >> 4;   // y slot:  j = ty + 16k within a tile

    const int rbase = blockIdx.x * BX + tx * 8;

    float xx[8], xy[8], xz[8], x2[8], rmin[8];
#pragma unroll
    for (int a = 0; a < 8; a++) {
        int r = rbase + a;
        bool v = (r < np);
        xx[a] = v ? X[3 * r + 0] : PAD_COORD;
        xy[a] = v ? X[3 * r + 1] : PAD_COORD;
        xz[a] = v ? X[3 * r + 2] : PAD_COORD;
        x2[a] = fmaf(xx[a], xx[a], fmaf(xy[a], xy[a], xz[a] * xz[a]));
        rmin[a] = __uint_as_float(INF_BITS);
    }

    const int ntiles = (m + TILE - 1) / TILE;
    for (int t = blockIdx.y; t < ntiles; t += GY) {
        const int jb = t * TILE;
        __syncthreads();   // protect sy from previous iteration's readers
        for (int i = tid; i < TILE; i += NTHREADS) {
            int j = jb + i;
            bool v = (j < m);
            float yx = v ? Y[3 * j + 0] : PAD_COORD;
            float yy = v ? Y[3 * j + 1] : PAD_COORD;
            float yz = v ? Y[3 * j + 2] : PAD_COORD;
            sy[4 * i + 0] = -2.0f * yx;
            sy[4 * i + 1] = -2.0f * yy;
            sy[4 * i + 2] = -2.0f * yz;
            sy[4 * i + 3] = fmaf(yx, yx, fmaf(yy, yy, yz * yz));
        }
        __syncthreads();

#pragma unroll
        for (int k = 0; k < 8; k++) {
            const int js = ty + k * 16;
            const float c0 = sy[4 * js + 0];
            const float c1 = sy[4 * js + 1];
            const float c2 = sy[4 * js + 2];
            const float w  = sy[4 * js + 3];

            float cmin = __uint_as_float(INF_BITS);
#pragma unroll
            for (int a = 0; a < 8; a++) {
                // xdot = x.x - 2 x.y   (3 FFMA)
                float xdot = fmaf(c0, xx[a],
                            fmaf(c1, xy[a],
                            fmaf(c2, xz[a], x2[a])));
                cmin    = fminf(cmin, xdot);            // w const over a
                rmin[a] = fminf(rmin[a], xdot + w);     // 1 FADD
            }

            // col-min: reduce across the 16 tx threads sharing this y slot
            // (lanes 0..15 / 16..31 of each warp form the groups)
#pragma unroll
            for (int off = 8; off >= 1; off >>= 1)
                cmin = fminf(cmin, __shfl_xor_sync(0xffffffffu, cmin, off, 16));
            if (tx == 0) {
                int j = jb + js;
                if (j < m)
                    atomicMin(&g_colmin[j],
                              __float_as_uint(fmaxf(cmin + w, 0.0f)));
            }
        }
    }

    // combine row mins across the 16 ty threads in shared, then one global
    // atomicMin per row (GY blocks contribute to the same row).
    if (tid < BX) srow[tid] = INF_BITS;
    __syncthreads();
#pragma unroll
    for (int a = 0; a < 8; a++)
        atomicMin(&srow[tx * 8 + a],
                  __float_as_uint(fmaxf(rmin[a], 0.0f)));
    __syncthreads();
    if (tid < BX) {
        int r = blockIdx.x * BX + tid;
        if (r < np) atomicMin(&g_rowmin[r], srow[tid]);
    }
}

__global__ void __launch_bounds__(256) chamfer_reduce(float* out, int np, int m)
{
    __shared__ float ssum[256];
    const int tid = threadIdx.x;
    float s_row = 0.0f, s_col = 0.0f;
    for (int i = tid; i < np; i += 256)
        s_row += sqrtf(__uint_as_float(g_rowmin[i]));
    for (int i = tid; i < m; i += 256)
        s_col += sqrtf(__uint_as_float(g_colmin[i]));
    float c = s_row / (float)np + s_col / (float)m;
    ssum[tid] = c;
    __syncthreads();
    for (int off = 128; off >= 1; off >>= 1) {
        if (tid < off) ssum[tid] += ssum[tid + off];
        __syncthreads();
    }
    if (tid == 0) out[0] = ssum[0];
}

extern "C" void kernel_launch(void* const* d_in, const int* in_sizes, int n_in,
                              void* d_out, int out_size) {
    const float* pred = (const float*)d_in[0];
    const float* gt   = (const float*)d_in[1];
    float* out = (float*)d_out;

    int np = in_sizes[0] / 3;   // 2048*8 = 16384 points
    int m  = in_sizes[1] / 3;

    int nmax = np > m ? np : m;
    chamfer_init<<<(nmax + 255) / 256, 256>>>(np, m);

    dim3 grid((np + BX - 1) / BX, GY);
    chamfer_main<<<grid, NTHREADS>>>(pred, gt, np, m);

    chamfer_reduce<<<1, 256>>>(out, np, m);
}

// round 4
// speedup vs baseline: 1.3300x; 1.3300x over previous
#include <cuda_runtime.h>
#include <math.h>

// ---------------------------------------------------------------------------
// ChamferLoss bidirectional chamfer distance, f32, Np=Ng=16384 points.
//
// out = mean_i sqrt(min_j d2_ij) + mean_j sqrt(min_i d2_ij)
// d2 = |x|^2 + |y|^2 - 2 x.y   (expansion form, matches reference math)
//
// R4: packed f32x2 inner loop (fma.rn.f32x2 / add.rn.f32x2 — 2 x-rows per
// instr), float4 coefficient loads, GY=4 grid split for latency hiding.
// Per 2 pairs: 3 FFMA2 + 1 FADD2 (fma pipe) + 4 FMNMX (alu pipe).
//   - col-min tracks xdot = |x|^2 - 2 x.y (w_j const over rows; added after
//     the shfl reduction), row-min tracks xdot + w (FADD2).
//   - mins over d2; sqrt only at the end. d2 can be slightly negative ->
//     clamp at reduction boundaries (uint-bit atomicMin needs >= 0 floats).
// ---------------------------------------------------------------------------

#define BX   128     // x rows per block
#define TILE 128     // y points per shared tile
#define GY   4       // y-direction split (512 CTAs total)
#define NTHREADS 256
#define INF_BITS 0x7f800000u
#define PAD_COORD 1.0e18f

typedef unsigned long long ull;

__device__ __forceinline__ ull pack2(float lo, float hi) {
    ull r; asm("mov.b64 %0, {%1, %2};" : "=l"(r) : "f"(lo), "f"(hi)); return r;
}
__device__ __forceinline__ void unpack2(ull v, float& lo, float& hi) {
    asm("mov.b64 {%0, %1}, %2;" : "=f"(lo), "=f"(hi) : "l"(v));
}
__device__ __forceinline__ ull fma2(ull a, ull b, ull c) {
    ull d; asm("fma.rn.f32x2 %0, %1, %2, %3;" : "=l"(d) : "l"(a), "l"(b), "l"(c));
    return d;
}
__device__ __forceinline__ ull add2(ull a, ull b) {
    ull d; asm("add.rn.f32x2 %0, %1, %2;" : "=l"(d) : "l"(a), "l"(b));
    return d;
}

__device__ unsigned g_rowmin[65536];
__device__ unsigned g_colmin[65536];

__global__ void chamfer_init(int np, int m) {
    int i = blockIdx.x * blockDim.x + threadIdx.x;
    if (i < np) g_rowmin[i] = INF_BITS;
    if (i < m)  g_colmin[i] = INF_BITS;
}

__global__ void __launch_bounds__(NTHREADS) chamfer_main(
    const float* __restrict__ X, const float* __restrict__ Y,
    int np, int m)
{
    __shared__ __align__(16) float4 sy4[TILE];   // {-2yx, -2yy, -2yz, |y|^2}
    __shared__ unsigned srow[BX];

    const int tid = threadIdx.x;
    const int tx = tid & 15;   // x group: rows tx*8 .. tx*8+7 of this block
    const int ty = tid >> 4;   // y slot:  j = ty + 16k within a tile

    const int rbase = blockIdx.x * BX + tx * 8;

    // packed coords for 8 rows = 4 f32x2 pairs
    ull xxp[4], xyp[4], xzp[4], x2p[4];
    float rmin[8];
#pragma unroll
    for (int p = 0; p < 4; p++) {
        float cx[2], cy[2], cz[2], c2[2];
#pragma unroll
        for (int h = 0; h < 2; h++) {
            int r = rbase + 2 * p + h;
            bool v = (r < np);
            cx[h] = v ? X[3 * r + 0] : PAD_COORD;
            cy[h] = v ? X[3 * r + 1] : PAD_COORD;
            cz[h] = v ? X[3 * r + 2] : PAD_COORD;
            c2[h] = fmaf(cx[h], cx[h], fmaf(cy[h], cy[h], cz[h] * cz[h]));
            rmin[2 * p + h] = __uint_as_float(INF_BITS);
        }
        xxp[p] = pack2(cx[0], cx[1]);
        xyp[p] = pack2(cy[0], cy[1]);
        xzp[p] = pack2(cz[0], cz[1]);
        x2p[p] = pack2(c2[0], c2[1]);
    }

    const int ntiles = (m + TILE - 1) / TILE;
    for (int t = blockIdx.y; t < ntiles; t += GY) {
        const int jb = t * TILE;
        __syncthreads();   // protect sy4 from previous iteration's readers
        for (int i = tid; i < TILE; i += NTHREADS) {
            int j = jb + i;
            bool v = (j < m);
            float yx = v ? Y[3 * j + 0] : PAD_COORD;
            float yy = v ? Y[3 * j + 1] : PAD_COORD;
            float yz = v ? Y[3 * j + 2] : PAD_COORD;
            sy4[i] = make_float4(-2.0f * yx, -2.0f * yy, -2.0f * yz,
                                 fmaf(yx, yx, fmaf(yy, yy, yz * yz)));
        }
        __syncthreads();

#pragma unroll
        for (int k = 0; k < 8; k++) {
            const int js = ty + k * 16;
            const float4 c = sy4[js];                 // one LDS.128
            const ull c0p = pack2(c.x, c.x);
            const ull c1p = pack2(c.y, c.y);
            const ull c2p = pack2(c.z, c.z);
            const ull wp  = pack2(c.w, c.w);

            float cmin = __uint_as_float(INF_BITS);
#pragma unroll
            for (int p = 0; p < 4; p++) {
                // xdot2 = |x|^2 - 2 x.y   (3 FFMA2)
                ull xd = fma2(c0p, xxp[p],
                         fma2(c1p, xyp[p],
                         fma2(c2p, xzp[p], x2p[p])));
                float lo, hi; unpack2(xd, lo, hi);
                cmin = fminf(cmin, fminf(lo, hi));    // 2 FMNMX (tree)
                ull d2 = add2(xd, wp);                // 1 FADD2
                float dlo, dhi; unpack2(d2, dlo, dhi);
                rmin[2 * p + 0] = fminf(rmin[2 * p + 0], dlo);
                rmin[2 * p + 1] = fminf(rmin[2 * p + 1], dhi);
            }

            // col-min: reduce across the 16 tx threads sharing this y slot
#pragma unroll
            for (int off = 8; off >= 1; off >>= 1)
                cmin = fminf(cmin, __shfl_xor_sync(0xffffffffu, cmin, off, 16));
            if (tx == 0) {
                int j = jb + js;
                if (j < m)
                    atomicMin(&g_colmin[j],
                              __float_as_uint(fmaxf(cmin + c.w, 0.0f)));
            }
        }
    }

    // combine row mins across the 16 ty threads in shared, then one global
    // atomicMin per row (GY blocks contribute to each row).
    if (tid < BX) srow[tid] = INF_BITS;
    __syncthreads();
#pragma unroll
    for (int a = 0; a < 8; a++)
        atomicMin(&srow[tx * 8 + a],
                  __float_as_uint(fmaxf(rmin[a], 0.0f)));
    __syncthreads();
    if (tid < BX) {
        int r = blockIdx.x * BX + tid;
        if (r < np) atomicMin(&g_rowmin[r], srow[tid]);
    }
}

__global__ void __launch_bounds__(256) chamfer_reduce(float* out, int np, int m)
{
    __shared__ float ssum[256];
    const int tid = threadIdx.x;
    float s_row = 0.0f, s_col = 0.0f;
    for (int i = tid; i < np; i += 256)
        s_row += sqrtf(__uint_as_float(g_rowmin[i]));
    for (int i = tid; i < m; i += 256)
        s_col += sqrtf(__uint_as_float(g_colmin[i]));
    float c = s_row / (float)np + s_col / (float)m;
    ssum[tid] = c;
    __syncthreads();
    for (int off = 128; off >= 1; off >>= 1) {
        if (tid < off) ssum[tid] += ssum[tid + off];
        __syncthreads();
    }
    if (tid == 0) out[0] = ssum[0];
}

extern "C" void kernel_launch(void* const* d_in, const int* in_sizes, int n_in,
                              void* d_out, int out_size) {
    const float* pred = (const float*)d_in[0];
    const float* gt   = (const float*)d_in[1];
    float* out = (float*)d_out;

    int np = in_sizes[0] / 3;   // 16384
    int m  = in_sizes[1] / 3;

    int nmax = np > m ? np : m;
    chamfer_init<<<(nmax + 255) / 256, 256>>>(np, m);

    dim3 grid((np + BX - 1) / BX, GY);
    chamfer_main<<<grid, NTHREADS>>>(pred, gt, np, m);

    chamfer_reduce<<<1, 256>>>(out, np, m);
}